// round 15
// baseline (speedup 1.0000x reference)
#include <cuda_runtime.h>
#include <cuda_fp16.h>
#include <math.h>
#include <stdint.h>

// Problem constants
#define Bc   2
#define Mc   2048
#define Dc   1024
#define Hc   16
#define DHc  64
#define FFc  2624
#define ROWS (Bc * Mc)      // 4096
#define QKVN (3 * Dc)       // 3072
#define WIN  (2 * FFc)      // 5248

// ---------------- scratch (device globals; no cudaMalloc allowed) ----------------
__device__ __align__(16) float  g_qkv [ROWS * QKVN];            // fp32 (rope + attn)
__device__ __align__(16) float  g_x1  [ROWS * Dc];              // fp32 residual
__device__ __align__(16) float  g_g   [(size_t)ROWS * WIN];     // fp32 WI output
__device__ __align__(16) __half h_xn  [ROWS * Dc];
__device__ __align__(16) __half h_attn[ROWS * Dc];
__device__ __align__(16) __half h_h   [ROWS * Dc];
__device__ __align__(16) __half h_act [(size_t)ROWS * FFc];
__device__ __align__(16) __half hw_qkv[QKVN * Dc];
__device__ __align__(16) __half hw_o  [Dc * Dc];
__device__ __align__(16) __half hw_i  [(size_t)WIN * Dc];
__device__ __align__(16) __half hw_om [Dc * FFc];

// ---------------- asm helpers ----------------
__device__ __forceinline__ void mma_f16(float* c, const uint32_t* a, const uint32_t* b) {
    asm volatile(
        "mma.sync.aligned.m16n8k16.row.col.f32.f16.f16.f32 "
        "{%0,%1,%2,%3}, {%4,%5,%6,%7}, {%8,%9}, {%0,%1,%2,%3};"
        : "+f"(c[0]), "+f"(c[1]), "+f"(c[2]), "+f"(c[3])
        : "r"(a[0]), "r"(a[1]), "r"(a[2]), "r"(a[3]), "r"(b[0]), "r"(b[1]));
}
#define LDSM_X4(d0,d1,d2,d3,addr) \
    asm volatile("ldmatrix.sync.aligned.m8n8.x4.shared.b16 {%0,%1,%2,%3}, [%4];" \
        : "=r"(d0),"=r"(d1),"=r"(d2),"=r"(d3) : "r"(addr))
#define LDSM_X2(d0,d1,addr) \
    asm volatile("ldmatrix.sync.aligned.m8n8.x2.shared.b16 {%0,%1}, [%2];" \
        : "=r"(d0),"=r"(d1) : "r"(addr))
#define CP_ASYNC16(smem,gptr) \
    asm volatile("cp.async.cg.shared.global [%0], [%1], 16;" :: "r"(smem), "l"(gptr))
#define CP_COMMIT() asm volatile("cp.async.commit_group;")
#define CP_WAIT1()  asm volatile("cp.async.wait_group 1;")
#define CP_WAIT0()  asm volatile("cp.async.wait_group 0;")

// ---------------- MUFU-free exp: FMA-pipe polynomial (rel err ~2e-6) ----------------
__device__ __forceinline__ float fexp(float x) {
    float z = x * 1.4426950408889634f;          // log2(e)
    z = fmaxf(z, -126.0f);
    float r = z + 12582912.0f;                  // round-to-nearest via magic
    int   i = __float_as_int(r) << 23;          // n << 23 (exponent offset)
    float f = z - (r - 12582912.0f);            // frac in [-0.5, 0.5]
    float p =            1.3333558e-3f;         // ln2^5/120
    p = fmaf(p, f, 9.6181291e-3f);              // ln2^4/24
    p = fmaf(p, f, 5.5504109e-2f);              // ln2^3/6
    p = fmaf(p, f, 2.4022651e-1f);              // ln2^2/2
    p = fmaf(p, f, 6.9314718e-1f);              // ln2
    p = fmaf(p, f, 1.0f);
    return __int_as_float(__float_as_int(p) + i);
}

// ======== fp16 tensor NT GEMM: C[M,Nd] = A[M,Kd] @ B[Nd,Kd]^T (+bias)(+res) ========
// BM=BN=128, BK=32, 256 threads (8 warps 2x4), warp tile 64x32 = 4x4 m16n8k16.
// cp.async double buffer + ldmatrix fragments; HSTR=40 halves -> conflict-free.
#define HSTR 40
__global__ void __launch_bounds__(256, 2) gemm_h2(const __half* __restrict__ A,
                                                  const __half* __restrict__ Bw,
                                                  const float* __restrict__ bias,
                                                  const float* __restrict__ res,
                                                  float* __restrict__ C,
                                                  int Nd, int Kd) {
    __shared__ __align__(16) __half As[2][128 * HSTR];
    __shared__ __align__(16) __half Bs[2][128 * HSTR];

    const int t    = threadIdx.x;
    const int lane = t & 31;
    const int warp = t >> 5;
    const int wm   = (warp & 1) * 64;
    const int wn   = (warp >> 1) * 32;

    const int m0 = blockIdx.y * 128;
    const int n0 = blockIdx.x * 128;

    // loader mapping: 2 threads/row, 16 halves (32B) each -> two 16B cp.async
    const int lrow = t >> 1;
    const int lcol = (t & 1) * 16;
    const __half* Ap = A  + (size_t)(m0 + lrow) * Kd + lcol;
    const __half* Bp = Bw + (size_t)(n0 + lrow) * Kd + lcol;

    uint32_t sA[2], sB[2];
    sA[0] = (uint32_t)__cvta_generic_to_shared(&As[0][0]);
    sA[1] = (uint32_t)__cvta_generic_to_shared(&As[1][0]);
    sB[0] = (uint32_t)__cvta_generic_to_shared(&Bs[0][0]);
    sB[1] = (uint32_t)__cvta_generic_to_shared(&Bs[1][0]);
    const uint32_t stoff = (uint32_t)(lrow * HSTR + lcol) * 2;

    // ldmatrix source addresses (byte offsets within one buffer)
    const int arow = wm + (lane & 15);
    const int acol = ((lane >> 4) & 1) * 8;
    const int brow = wn + (lane & 7);
    const int bcol = ((lane >> 3) & 1) * 8;

    float acc[4][4][4];
    #pragma unroll
    for (int mt = 0; mt < 4; mt++)
        #pragma unroll
        for (int nt = 0; nt < 4; nt++)
            #pragma unroll
            for (int c = 0; c < 4; c++) acc[mt][nt][c] = 0.f;

    const int nch = Kd >> 5;
    // prologue: chunk 0 -> buf 0
    CP_ASYNC16(sA[0] + stoff,      Ap);
    CP_ASYNC16(sA[0] + stoff + 16, Ap + 8);
    CP_ASYNC16(sB[0] + stoff,      Bp);
    CP_ASYNC16(sB[0] + stoff + 16, Bp + 8);
    CP_COMMIT();

    for (int i = 0; i < nch; i++) {
        const int b = i & 1;
        if (i + 1 < nch) {
            const int nb = (i + 1) & 1;
            const __half* An = Ap + (i + 1) * 32;
            const __half* Bn = Bp + (i + 1) * 32;
            CP_ASYNC16(sA[nb] + stoff,      An);
            CP_ASYNC16(sA[nb] + stoff + 16, An + 8);
            CP_ASYNC16(sB[nb] + stoff,      Bn);
            CP_ASYNC16(sB[nb] + stoff + 16, Bn + 8);
            CP_COMMIT();
            CP_WAIT1();
        } else {
            CP_WAIT0();
        }
        __syncthreads();

        #pragma unroll
        for (int ks = 0; ks < 2; ks++) {
            const int koff = ks * 16;
            uint32_t af[4][4], bf[4][2];
            #pragma unroll
            for (int mt = 0; mt < 4; mt++) {
                uint32_t ad = sA[b] + (uint32_t)(((arow + mt * 16) * HSTR) + koff + acol) * 2;
                LDSM_X4(af[mt][0], af[mt][1], af[mt][2], af[mt][3], ad);
            }
            #pragma unroll
            for (int nt = 0; nt < 4; nt++) {
                uint32_t bd = sB[b] + (uint32_t)(((brow + nt * 8) * HSTR) + koff + bcol) * 2;
                LDSM_X2(bf[nt][0], bf[nt][1], bd);
            }
            #pragma unroll
            for (int mt = 0; mt < 4; mt++)
                #pragma unroll
                for (int nt = 0; nt < 4; nt++)
                    mma_f16(acc[mt][nt], af[mt], bf[nt]);
        }
        __syncthreads();   // compute done before this buffer is refilled
    }

    // epilogue
    const int gid = lane >> 2;
    const int tig = lane & 3;
    #pragma unroll
    for (int mt = 0; mt < 4; mt++) {
        #pragma unroll
        for (int hf = 0; hf < 2; hf++) {
            const int gm = m0 + wm + mt * 16 + gid + hf * 8;
            float* Cp = C + (size_t)gm * Nd + n0 + wn;
            const float* Rp = res ? res + (size_t)gm * Nd + n0 + wn : nullptr;
            #pragma unroll
            for (int nt = 0; nt < 4; nt++) {
                const int cc = nt * 8 + 2 * tig;
                float v0 = acc[mt][nt][hf * 2 + 0];
                float v1 = acc[mt][nt][hf * 2 + 1];
                if (bias) {
                    v0 += bias[n0 + wn + cc];
                    v1 += bias[n0 + wn + cc + 1];
                }
                if (Rp) {
                    v0 += Rp[cc];
                    v1 += Rp[cc + 1];
                }
                *(float2*)(Cp + cc) = make_float2(v0, v1);
            }
        }
    }
}

// ---------------- weight convert fp32 -> fp16 ----------------
__global__ void wcvt(const float* __restrict__ w, __half* __restrict__ o, int n4) {
    int idx = blockIdx.x * blockDim.x + threadIdx.x;
    if (idx >= n4) return;
    float4 v = ((const float4*)w)[idx];
    half2 a = __float22half2_rn(make_float2(v.x, v.y));
    half2 b = __float22half2_rn(make_float2(v.z, v.w));
    ((uint2*)o)[idx] = make_uint2(*(uint32_t*)&a, *(uint32_t*)&b);
}

// ---------------- LayerNorm (fp16 out) ----------------
__global__ void __launch_bounds__(256) ln_kernel(const float* __restrict__ x,
                                                 const float* __restrict__ w,
                                                 const float* __restrict__ b,
                                                 __half* __restrict__ out) {
    int row = blockIdx.x;
    int t = threadIdx.x;
    const float4* xr = reinterpret_cast<const float4*>(x + (size_t)row * Dc);
    float4 v = xr[t];
    float s  = v.x + v.y + v.z + v.w;
    float ss = v.x * v.x + v.y * v.y + v.z * v.z + v.w * v.w;

    __shared__ float red0[8], red1[8];
    #pragma unroll
    for (int o = 16; o; o >>= 1) {
        s  += __shfl_xor_sync(0xffffffffu, s,  o);
        ss += __shfl_xor_sync(0xffffffffu, ss, o);
    }
    int wid = t >> 5, lid = t & 31;
    if (lid == 0) { red0[wid] = s; red1[wid] = ss; }
    __syncthreads();
    if (t == 0) {
        float a = 0.f, c = 0.f;
        #pragma unroll
        for (int i = 0; i < 8; i++) { a += red0[i]; c += red1[i]; }
        red0[0] = a; red1[0] = c;
    }
    __syncthreads();
    s = red0[0]; ss = red1[0];
    float mu   = s * (1.0f / Dc);
    float var  = ss * (1.0f / Dc) - mu * mu;
    float rstd = rsqrtf(var + 1e-5f);

    const float4* w4 = reinterpret_cast<const float4*>(w);
    const float4* b4 = reinterpret_cast<const float4*>(b);
    float4 ww = w4[t], bb = b4[t];
    half2 o0 = __float22half2_rn(make_float2((v.x - mu) * rstd * ww.x + bb.x,
                                             (v.y - mu) * rstd * ww.y + bb.y));
    half2 o1 = __float22half2_rn(make_float2((v.z - mu) * rstd * ww.z + bb.z,
                                             (v.w - mu) * rstd * ww.w + bb.w));
    ((uint2*)(out + (size_t)row * Dc))[t] = make_uint2(*(uint32_t*)&o0, *(uint32_t*)&o1);
}

// ---------------- RoPE ----------------
__global__ void rope_kernel(float* __restrict__ qkv) {
    int idx = blockIdx.x * blockDim.x + threadIdx.x;
    if (idx >= ROWS * Hc * (DHc / 2)) return;
    int j   = idx & 31;
    int h   = (idx >> 5) & (Hc - 1);
    int row = idx >> 9;
    int m   = row & (Mc - 1);

    float inv_freq = powf(10000.0f, -(float)(2 * j) / (float)DHc);
    float freq = (float)m * inv_freq;
    float sn, cs;
    sincosf(freq, &sn, &cs);

    float* qp = qkv + (size_t)row * QKVN + h * DHc;
    float* kp = qp + Dc;
    float q1 = qp[j], q2 = qp[32 + j];
    qp[j]      = q1 * cs - q2 * sn;
    qp[32 + j] = q1 * sn + q2 * cs;
    float k1 = kp[j], k2 = kp[32 + j];
    kp[j]      = k1 * cs - k2 * sn;
    kp[32 + j] = k1 * sn + k2 * cs;
}

// ---------------- Flash attention: 128x128 tiles, 8x8 register blocking (fp16 out) ----------------
#define PBS 136
#define F_QT 0
#define F_KT 8192
#define F_VS 16384
#define F_PB 24576
#define F_MSK (F_PB + 128 * PBS)
#define ATTN_SMEM_BYTES ((F_MSK + 128) * 4)

__global__ void __launch_bounds__(256) attn_kernel(const float* __restrict__ qkv,
                                                   const int* __restrict__ mask,
                                                   __half* __restrict__ out) {
    extern __shared__ __align__(16) float sh[];
    float* Qt = sh + F_QT;
    float* Kt = sh + F_KT;
    float* Vs = sh + F_VS;
    float* Pb = sh + F_PB;
    int*   msk = reinterpret_cast<int*>(sh + F_MSK);

    const int m0 = blockIdx.x * 128;
    const int h  = blockIdx.y;
    const int b  = blockIdx.z;
    const int t  = threadIdx.x;
    const int ty = t >> 4;
    const int tx = t & 15;

    const float* qbase = qkv + (size_t)(b * Mc + m0) * QKVN + h * DHc;
    const float* kbase = qkv + (size_t)(b * Mc) * QKVN + Dc + h * DHc;
    const float* vbase = kbase + Dc;
    const int*   mbase = mask + b * Mc;

    {
        const int r   = t & 127;
        const int sg0 = t >> 7;
        const float* qrow = qbase + (size_t)r * QKVN;
        #pragma unroll
        for (int sg = sg0; sg < 16; sg += 2) {
            float4 v = *(const float4*)(qrow + sg * 4);
            Qt[(sg * 4 + 0) * 128 + r] = v.x * 0.125f;
            Qt[(sg * 4 + 1) * 128 + r] = v.y * 0.125f;
            Qt[(sg * 4 + 2) * 128 + r] = v.z * 0.125f;
            Qt[(sg * 4 + 3) * 128 + r] = v.w * 0.125f;
        }
    }

    float mreg[8], lreg[8], oacc[8][4];
    #pragma unroll
    for (int i = 0; i < 8; i++) {
        mreg[i] = -1e30f; lreg[i] = 0.f;
        oacc[i][0] = oacc[i][1] = oacc[i][2] = oacc[i][3] = 0.f;
    }

    for (int n0 = 0; n0 < Mc; n0 += 128) {
        __syncthreads();
        int myv = 0;
        if (t < 128) { int mv = mbase[n0 + t]; msk[t] = mv; myv = (mv != 0); }
        int any = __syncthreads_or(myv);
        if (!any) continue;

        {
            const int r   = t & 127;
            const int sg0 = t >> 7;
            const float* krow = kbase + (size_t)(n0 + r) * QKVN;
            #pragma unroll
            for (int sg = sg0; sg < 16; sg += 2) {
                float4 v = *(const float4*)(krow + sg * 4);
                Kt[(sg * 4 + 0) * 128 + r] = v.x;
                Kt[(sg * 4 + 1) * 128 + r] = v.y;
                Kt[(sg * 4 + 2) * 128 + r] = v.z;
                Kt[(sg * 4 + 3) * 128 + r] = v.w;
            }
        }
        #pragma unroll
        for (int idx = t, it = 0; it < 8; idx += 256, it++) {
            int r = idx >> 4, sg = idx & 15;
            *(float4*)&Vs[r * 64 + sg * 4] =
                *(const float4*)(vbase + (size_t)(n0 + r) * QKVN + sg * 4);
        }
        __syncthreads();

        float s[8][8];
        #pragma unroll
        for (int i = 0; i < 8; i++)
            #pragma unroll
            for (int j = 0; j < 8; j++) s[i][j] = 0.f;

        #pragma unroll 4
        for (int d = 0; d < 64; d++) {
            float av[8], bv[8];
            *(float4*)(av)     = *(const float4*)&Qt[d * 128 + ty * 8];
            *(float4*)(av + 4) = *(const float4*)&Qt[d * 128 + ty * 8 + 4];
            *(float4*)(bv)     = *(const float4*)&Kt[d * 128 + tx * 8];
            *(float4*)(bv + 4) = *(const float4*)&Kt[d * 128 + tx * 8 + 4];
            #pragma unroll
            for (int i = 0; i < 8; i++)
                #pragma unroll
                for (int j = 0; j < 8; j++) s[i][j] += av[i] * bv[j];
        }

        bool val[8];
        #pragma unroll
        for (int j = 0; j < 8; j++) val[j] = (msk[tx * 8 + j] != 0);

        float scr[8];
        #pragma unroll
        for (int i = 0; i < 8; i++) {
            float tm = -1e30f;
            #pragma unroll
            for (int j = 0; j < 8; j++) if (val[j]) tm = fmaxf(tm, s[i][j]);
            tm = fmaxf(tm, __shfl_xor_sync(0xffffffffu, tm, 1));
            tm = fmaxf(tm, __shfl_xor_sync(0xffffffffu, tm, 2));
            tm = fmaxf(tm, __shfl_xor_sync(0xffffffffu, tm, 4));
            tm = fmaxf(tm, __shfl_xor_sync(0xffffffffu, tm, 8));
            float mn = fmaxf(mreg[i], tm);
            float sc = fexp(mreg[i] - mn);
            float rs = 0.f;
            #pragma unroll
            for (int j = 0; j < 8; j++) {
                float p = val[j] ? fexp(s[i][j] - mn) : 0.f;
                s[i][j] = p;
                rs += p;
            }
            rs += __shfl_xor_sync(0xffffffffu, rs, 1);
            rs += __shfl_xor_sync(0xffffffffu, rs, 2);
            rs += __shfl_xor_sync(0xffffffffu, rs, 4);
            rs += __shfl_xor_sync(0xffffffffu, rs, 8);
            lreg[i] = lreg[i] * sc + rs;
            mreg[i] = mn;
            scr[i]  = sc;
            *(float4*)&Pb[(ty * 8 + i) * PBS + tx * 8]     =
                make_float4(s[i][0], s[i][1], s[i][2], s[i][3]);
            *(float4*)&Pb[(ty * 8 + i) * PBS + tx * 8 + 4] =
                make_float4(s[i][4], s[i][5], s[i][6], s[i][7]);
        }
        __syncthreads();

        #pragma unroll
        for (int i = 0; i < 8; i++) {
            oacc[i][0] *= scr[i]; oacc[i][1] *= scr[i];
            oacc[i][2] *= scr[i]; oacc[i][3] *= scr[i];
        }
        #pragma unroll 2
        for (int kc = 0; kc < 128; kc += 4) {
            float4 v0 = *(const float4*)&Vs[(kc + 0) * 64 + tx * 4];
            float4 v1 = *(const float4*)&Vs[(kc + 1) * 64 + tx * 4];
            float4 v2 = *(const float4*)&Vs[(kc + 2) * 64 + tx * 4];
            float4 v3 = *(const float4*)&Vs[(kc + 3) * 64 + tx * 4];
            #pragma unroll
            for (int i = 0; i < 8; i++) {
                float4 p4 = *(const float4*)&Pb[(ty * 8 + i) * PBS + kc];
                oacc[i][0] += p4.x * v0.x; oacc[i][1] += p4.x * v0.y;
                oacc[i][2] += p4.x * v0.z; oacc[i][3] += p4.x * v0.w;
                oacc[i][0] += p4.y * v1.x; oacc[i][1] += p4.y * v1.y;
                oacc[i][2] += p4.y * v1.z; oacc[i][3] += p4.y * v1.w;
                oacc[i][0] += p4.z * v2.x; oacc[i][1] += p4.z * v2.y;
                oacc[i][2] += p4.z * v2.z; oacc[i][3] += p4.z * v2.w;
                oacc[i][0] += p4.w * v3.x; oacc[i][1] += p4.w * v3.y;
                oacc[i][2] += p4.w * v3.z; oacc[i][3] += p4.w * v3.w;
            }
        }
    }

    #pragma unroll
    for (int i = 0; i < 8; i++) {
        float inv = 1.0f / lreg[i];
        __half* op = out + (size_t)(b * Mc + m0 + ty * 8 + i) * Dc + h * DHc + tx * 4;
        half2 h0 = __float22half2_rn(make_float2(oacc[i][0] * inv, oacc[i][1] * inv));
        half2 h1 = __float22half2_rn(make_float2(oacc[i][2] * inv, oacc[i][3] * inv));
        *(uint2*)op = make_uint2(*(uint32_t*)&h0, *(uint32_t*)&h1);
    }
}

// ---------------- GeGLU (exact gelu * gate, fp16 out) ----------------
__global__ void geglu_kernel(const float* __restrict__ g, __half* __restrict__ act) {
    int idx = blockIdx.x * blockDim.x + threadIdx.x;
    if (idx >= ROWS * FFc) return;
    int r = idx / FFc;
    int j = idx - r * FFc;
    float x    = g[(size_t)r * WIN + j];
    float gate = g[(size_t)r * WIN + FFc + j];
    float ge = 0.5f * x * (1.0f + erff(x * 0.7071067811865476f));
    act[idx] = __float2half_rn(ge * gate);
}

// ---------------- launch ----------------
extern "C" void kernel_launch(void* const* d_in, const int* in_sizes, int n_in,
                              void* d_out, int out_size) {
    const float* x     = (const float*)d_in[0];
    const int*   mask  = (const int*)  d_in[1];
    const float* ln1w  = (const float*)d_in[2];
    const float* ln1b  = (const float*)d_in[3];
    const float* wqkv  = (const float*)d_in[4];
    const float* bqkv  = (const float*)d_in[5];
    const float* wo    = (const float*)d_in[6];
    const float* ln2w  = (const float*)d_in[7];
    const float* ln2b  = (const float*)d_in[8];
    const float* wi    = (const float*)d_in[9];
    const float* womlp = (const float*)d_in[10];
    float* out = (float*)d_out;

    float *qkvb, *x1, *gb;
    __half *xn, *attn, *hb, *actb, *wq, *wO, *wI, *wOM;
    cudaGetSymbolAddress((void**)&qkvb, g_qkv);
    cudaGetSymbolAddress((void**)&x1,   g_x1);
    cudaGetSymbolAddress((void**)&gb,   g_g);
    cudaGetSymbolAddress((void**)&xn,   h_xn);
    cudaGetSymbolAddress((void**)&attn, h_attn);
    cudaGetSymbolAddress((void**)&hb,   h_h);
    cudaGetSymbolAddress((void**)&actb, h_act);
    cudaGetSymbolAddress((void**)&wq,   hw_qkv);
    cudaGetSymbolAddress((void**)&wO,   hw_o);
    cudaGetSymbolAddress((void**)&wI,   hw_i);
    cudaGetSymbolAddress((void**)&wOM,  hw_om);

    cudaFuncSetAttribute(attn_kernel, cudaFuncAttributeMaxDynamicSharedMemorySize,
                         ATTN_SMEM_BYTES);

    // 0. weight conversions
    wcvt<<<(QKVN * Dc / 4 + 255) / 256, 256>>>(wqkv, wq, QKVN * Dc / 4);
    wcvt<<<(Dc * Dc / 4 + 255) / 256, 256>>>(wo, wO, Dc * Dc / 4);
    wcvt<<<((int)((size_t)WIN * Dc / 4) + 255) / 256, 256>>>(wi, wI, (int)((size_t)WIN * Dc / 4));
    wcvt<<<(Dc * FFc / 4 + 255) / 256, 256>>>(womlp, wOM, Dc * FFc / 4);

    // 1. LN1 -> fp16
    ln_kernel<<<ROWS, 256>>>(x, ln1w, ln1b, xn);
    // 2. QKV projection (+bias), fp32 out
    gemm_h2<<<dim3(QKVN / 128, ROWS / 128), 256>>>(xn, wq, bqkv, nullptr, qkvb, QKVN, Dc);
    // 3. RoPE
    rope_kernel<<<(ROWS * Hc * (DHc / 2) + 255) / 256, 256>>>(qkvb);
    // 4. Attention -> fp16
    attn_kernel<<<dim3(Mc / 128, Hc, Bc), 256, ATTN_SMEM_BYTES>>>(qkvb, mask, attn);
    // 5. WO projection + residual(x) -> fp32 x1
    gemm_h2<<<dim3(Dc / 128, ROWS / 128), 256>>>(attn, wO, nullptr, x, x1, Dc, Dc);
    // 6. LN2 -> fp16
    ln_kernel<<<ROWS, 256>>>(x1, ln2w, ln2b, hb);
    // 7. WI projection -> fp32 g
    gemm_h2<<<dim3(WIN / 128, ROWS / 128), 256>>>(hb, wI, nullptr, nullptr, gb, WIN, Dc);
    // 8. GeGLU -> fp16
    geglu_kernel<<<(ROWS * FFc + 255) / 256, 256>>>(gb, actb);
    // 9. WO_MLP projection + residual(x1) -> out
    gemm_h2<<<dim3(Dc / 128, ROWS / 128), 256>>>(actb, wOM, nullptr, x1, out, Dc, FFc);
}

// round 17
// speedup vs baseline: 1.9956x; 1.9956x over previous
#include <cuda_runtime.h>
#include <cuda_fp16.h>
#include <math.h>
#include <stdint.h>

// Problem constants
#define Bc   2
#define Mc   2048
#define Dc   1024
#define Hc   16
#define DHc  64
#define FFc  2624
#define ROWS (Bc * Mc)      // 4096
#define QKVN (3 * Dc)       // 3072
#define WIN  (2 * FFc)      // 5248

// ---------------- scratch (device globals; no cudaMalloc allowed) ----------------
__device__ __align__(16) float  g_qkv [ROWS * QKVN];            // fp32 (rope + attn)
__device__ __align__(16) float  g_x1  [ROWS * Dc];              // fp32 residual
__device__ __align__(16) float  g_g   [(size_t)ROWS * WIN];     // fp32 WI output
__device__ __align__(16) __half h_xn  [ROWS * Dc];
__device__ __align__(16) __half h_attn[ROWS * Dc];
__device__ __align__(16) __half h_h   [ROWS * Dc];
__device__ __align__(16) __half h_act [(size_t)ROWS * FFc];
__device__ __align__(16) __half hw_qkv[QKVN * Dc];
__device__ __align__(16) __half hw_o  [Dc * Dc];
__device__ __align__(16) __half hw_i  [(size_t)WIN * Dc];
__device__ __align__(16) __half hw_om [Dc * FFc];

// ---------------- asm helpers ----------------
__device__ __forceinline__ void mma_f16(float* c, const uint32_t* a, const uint32_t* b) {
    asm volatile(
        "mma.sync.aligned.m16n8k16.row.col.f32.f16.f16.f32 "
        "{%0,%1,%2,%3}, {%4,%5,%6,%7}, {%8,%9}, {%0,%1,%2,%3};"
        : "+f"(c[0]), "+f"(c[1]), "+f"(c[2]), "+f"(c[3])
        : "r"(a[0]), "r"(a[1]), "r"(a[2]), "r"(a[3]), "r"(b[0]), "r"(b[1]));
}
#define LDSM_X4(d0,d1,d2,d3,addr) \
    asm volatile("ldmatrix.sync.aligned.m8n8.x4.shared.b16 {%0,%1,%2,%3}, [%4];" \
        : "=r"(d0),"=r"(d1),"=r"(d2),"=r"(d3) : "r"(addr))
#define LDSM_X2(d0,d1,addr) \
    asm volatile("ldmatrix.sync.aligned.m8n8.x2.shared.b16 {%0,%1}, [%2];" \
        : "=r"(d0),"=r"(d1) : "r"(addr))
#define LDSM_X2T(d0,d1,addr) \
    asm volatile("ldmatrix.sync.aligned.m8n8.x2.trans.shared.b16 {%0,%1}, [%2];" \
        : "=r"(d0),"=r"(d1) : "r"(addr))
#define CP_ASYNC16(smem,gptr) \
    asm volatile("cp.async.cg.shared.global [%0], [%1], 16;" :: "r"(smem), "l"(gptr))
#define CP_COMMIT() asm volatile("cp.async.commit_group;")
#define CP_WAIT1()  asm volatile("cp.async.wait_group 1;")
#define CP_WAIT0()  asm volatile("cp.async.wait_group 0;")

__device__ __forceinline__ uint32_t h2u(float a, float b) {
    __half2 h = __float22half2_rn(make_float2(a, b));
    return *(uint32_t*)&h;
}

// ======== fp16 tensor NT GEMM: C[M,Nd] = A[M,Kd] @ B[Nd,Kd]^T (+bias)(+res) ========
#define HSTR 40
__global__ void __launch_bounds__(256, 2) gemm_h2(const __half* __restrict__ A,
                                                  const __half* __restrict__ Bw,
                                                  const float* __restrict__ bias,
                                                  const float* __restrict__ res,
                                                  float* __restrict__ C,
                                                  int Nd, int Kd) {
    __shared__ __align__(16) __half As[2][128 * HSTR];
    __shared__ __align__(16) __half Bs[2][128 * HSTR];

    const int t    = threadIdx.x;
    const int lane = t & 31;
    const int warp = t >> 5;
    const int wm   = (warp & 1) * 64;
    const int wn   = (warp >> 1) * 32;

    const int m0 = blockIdx.y * 128;
    const int n0 = blockIdx.x * 128;

    const int lrow = t >> 1;
    const int lcol = (t & 1) * 16;
    const __half* Ap = A  + (size_t)(m0 + lrow) * Kd + lcol;
    const __half* Bp = Bw + (size_t)(n0 + lrow) * Kd + lcol;

    uint32_t sA[2], sB[2];
    sA[0] = (uint32_t)__cvta_generic_to_shared(&As[0][0]);
    sA[1] = (uint32_t)__cvta_generic_to_shared(&As[1][0]);
    sB[0] = (uint32_t)__cvta_generic_to_shared(&Bs[0][0]);
    sB[1] = (uint32_t)__cvta_generic_to_shared(&Bs[1][0]);
    const uint32_t stoff = (uint32_t)(lrow * HSTR + lcol) * 2;

    const int arow = wm + (lane & 15);
    const int acol = ((lane >> 4) & 1) * 8;
    const int brow = wn + (lane & 7);
    const int bcol = ((lane >> 3) & 1) * 8;

    float acc[4][4][4];
    #pragma unroll
    for (int mt = 0; mt < 4; mt++)
        #pragma unroll
        for (int nt = 0; nt < 4; nt++)
            #pragma unroll
            for (int c = 0; c < 4; c++) acc[mt][nt][c] = 0.f;

    const int nch = Kd >> 5;
    CP_ASYNC16(sA[0] + stoff,      Ap);
    CP_ASYNC16(sA[0] + stoff + 16, Ap + 8);
    CP_ASYNC16(sB[0] + stoff,      Bp);
    CP_ASYNC16(sB[0] + stoff + 16, Bp + 8);
    CP_COMMIT();

    for (int i = 0; i < nch; i++) {
        const int b = i & 1;
        if (i + 1 < nch) {
            const int nb = (i + 1) & 1;
            const __half* An = Ap + (i + 1) * 32;
            const __half* Bn = Bp + (i + 1) * 32;
            CP_ASYNC16(sA[nb] + stoff,      An);
            CP_ASYNC16(sA[nb] + stoff + 16, An + 8);
            CP_ASYNC16(sB[nb] + stoff,      Bn);
            CP_ASYNC16(sB[nb] + stoff + 16, Bn + 8);
            CP_COMMIT();
            CP_WAIT1();
        } else {
            CP_WAIT0();
        }
        __syncthreads();

        #pragma unroll
        for (int ks = 0; ks < 2; ks++) {
            const int koff = ks * 16;
            uint32_t af[4][4], bf[4][2];
            #pragma unroll
            for (int mt = 0; mt < 4; mt++) {
                uint32_t ad = sA[b] + (uint32_t)(((arow + mt * 16) * HSTR) + koff + acol) * 2;
                LDSM_X4(af[mt][0], af[mt][1], af[mt][2], af[mt][3], ad);
            }
            #pragma unroll
            for (int nt = 0; nt < 4; nt++) {
                uint32_t bd = sB[b] + (uint32_t)(((brow + nt * 8) * HSTR) + koff + bcol) * 2;
                LDSM_X2(bf[nt][0], bf[nt][1], bd);
            }
            #pragma unroll
            for (int mt = 0; mt < 4; mt++)
                #pragma unroll
                for (int nt = 0; nt < 4; nt++)
                    mma_f16(acc[mt][nt], af[mt], bf[nt]);
        }
        __syncthreads();
    }

    const int gid = lane >> 2;
    const int tig = lane & 3;
    #pragma unroll
    for (int mt = 0; mt < 4; mt++) {
        #pragma unroll
        for (int hf = 0; hf < 2; hf++) {
            const int gm = m0 + wm + mt * 16 + gid + hf * 8;
            float* Cp = C + (size_t)gm * Nd + n0 + wn;
            const float* Rp = res ? res + (size_t)gm * Nd + n0 + wn : nullptr;
            #pragma unroll
            for (int nt = 0; nt < 4; nt++) {
                const int cc = nt * 8 + 2 * tig;
                float v0 = acc[mt][nt][hf * 2 + 0];
                float v1 = acc[mt][nt][hf * 2 + 1];
                if (bias) {
                    v0 += bias[n0 + wn + cc];
                    v1 += bias[n0 + wn + cc + 1];
                }
                if (Rp) {
                    v0 += Rp[cc];
                    v1 += Rp[cc + 1];
                }
                *(float2*)(Cp + cc) = make_float2(v0, v1);
            }
        }
    }
}

// ---------------- weight convert fp32 -> fp16 ----------------
__global__ void wcvt(const float* __restrict__ w, __half* __restrict__ o, int n4) {
    int idx = blockIdx.x * blockDim.x + threadIdx.x;
    if (idx >= n4) return;
    float4 v = ((const float4*)w)[idx];
    half2 a = __float22half2_rn(make_float2(v.x, v.y));
    half2 b = __float22half2_rn(make_float2(v.z, v.w));
    ((uint2*)o)[idx] = make_uint2(*(uint32_t*)&a, *(uint32_t*)&b);
}

// ---------------- LayerNorm (fp16 out) ----------------
__global__ void __launch_bounds__(256) ln_kernel(const float* __restrict__ x,
                                                 const float* __restrict__ w,
                                                 const float* __restrict__ b,
                                                 __half* __restrict__ out) {
    int row = blockIdx.x;
    int t = threadIdx.x;
    const float4* xr = reinterpret_cast<const float4*>(x + (size_t)row * Dc);
    float4 v = xr[t];
    float s  = v.x + v.y + v.z + v.w;
    float ss = v.x * v.x + v.y * v.y + v.z * v.z + v.w * v.w;

    __shared__ float red0[8], red1[8];
    #pragma unroll
    for (int o = 16; o; o >>= 1) {
        s  += __shfl_xor_sync(0xffffffffu, s,  o);
        ss += __shfl_xor_sync(0xffffffffu, ss, o);
    }
    int wid = t >> 5, lid = t & 31;
    if (lid == 0) { red0[wid] = s; red1[wid] = ss; }
    __syncthreads();
    if (t == 0) {
        float a = 0.f, c = 0.f;
        #pragma unroll
        for (int i = 0; i < 8; i++) { a += red0[i]; c += red1[i]; }
        red0[0] = a; red1[0] = c;
    }
    __syncthreads();
    s = red0[0]; ss = red1[0];
    float mu   = s * (1.0f / Dc);
    float var  = ss * (1.0f / Dc) - mu * mu;
    float rstd = rsqrtf(var + 1e-5f);

    const float4* w4 = reinterpret_cast<const float4*>(w);
    const float4* b4 = reinterpret_cast<const float4*>(b);
    float4 ww = w4[t], bb = b4[t];
    half2 o0 = __float22half2_rn(make_float2((v.x - mu) * rstd * ww.x + bb.x,
                                             (v.y - mu) * rstd * ww.y + bb.y));
    half2 o1 = __float22half2_rn(make_float2((v.z - mu) * rstd * ww.z + bb.z,
                                             (v.w - mu) * rstd * ww.w + bb.w));
    ((uint2*)(out + (size_t)row * Dc))[t] = make_uint2(*(uint32_t*)&o0, *(uint32_t*)&o1);
}

// ---------------- RoPE ----------------
__global__ void rope_kernel(float* __restrict__ qkv) {
    int idx = blockIdx.x * blockDim.x + threadIdx.x;
    if (idx >= ROWS * Hc * (DHc / 2)) return;
    int j   = idx & 31;
    int h   = (idx >> 5) & (Hc - 1);
    int row = idx >> 9;
    int m   = row & (Mc - 1);

    float inv_freq = powf(10000.0f, -(float)(2 * j) / (float)DHc);
    float freq = (float)m * inv_freq;
    float sn, cs;
    sincosf(freq, &sn, &cs);

    float* qp = qkv + (size_t)row * QKVN + h * DHc;
    float* kp = qp + Dc;
    float q1 = qp[j], q2 = qp[32 + j];
    qp[j]      = q1 * cs - q2 * sn;
    qp[32 + j] = q1 * sn + q2 * cs;
    float k1 = kp[j], k2 = kp[32 + j];
    kp[j]      = k1 * cs - k2 * sn;
    kp[32 + j] = k1 * sn + k2 * cs;
}

// ---------------- HMMA flash attention: 128 q/CTA, 128-key tiles ----------------
// 8 warps; warp w owns q rows [w*16, w*16+16). S and O live in mma fragments.
#define AHS 72                       // halves per smem row (64 + 8 skew)
#define AQ_OFF 0                     // Qh[128][AHS]
#define AK_OFF (128 * AHS)           // Kh[128][AHS]
#define AV_OFF (256 * AHS)           // Vh[128][AHS]
#define AMB_OFF (384 * AHS * 2)      // byte offset of float mb[128]
#define ATTN2_SMEM (AMB_OFF + 128 * 4)

__global__ void __launch_bounds__(256) attn2_kernel(const float* __restrict__ qkv,
                                                    const int* __restrict__ mask,
                                                    __half* __restrict__ out) {
    extern __shared__ __align__(16) __half shh[];
    __half* Qh = shh + AQ_OFF;
    __half* Kh = shh + AK_OFF;
    __half* Vh = shh + AV_OFF;
    float*  mb = (float*)((char*)shh + AMB_OFF);

    const int m0 = blockIdx.x * 128;
    const int h  = blockIdx.y;
    const int b  = blockIdx.z;
    const int t  = threadIdx.x;
    const int w    = t >> 5;
    const int lane = t & 31;
    const int gid  = lane >> 2;
    const int tig  = lane & 3;

    const float* qbase = qkv + (size_t)(b * Mc + m0) * QKVN + h * DHc;
    const float* kbase = qkv + (size_t)(b * Mc) * QKVN + Dc + h * DHc;
    const float* vbase = kbase + Dc;
    const int*   mbase = mask + b * Mc;

    const uint32_t sQ = (uint32_t)__cvta_generic_to_shared(Qh);
    const uint32_t sK = (uint32_t)__cvta_generic_to_shared(Kh);
    const uint32_t sV = (uint32_t)__cvta_generic_to_shared(Vh);

    // load Q -> fp16 smem (scaled by 1/sqrt(DH))
    for (int idx = t; idx < 2048; idx += 256) {
        int r = idx >> 4, sg = idx & 15;
        float4 v = *(const float4*)(qbase + (size_t)r * QKVN + sg * 4);
        __half* p = Qh + r * AHS + sg * 4;
        *(uint32_t*)(p)     = h2u(v.x * 0.125f, v.y * 0.125f);
        *(uint32_t*)(p + 2) = h2u(v.z * 0.125f, v.w * 0.125f);
    }

    float Sf[16][4];
    float Of[8][4];
    float mreg0 = -1e30f, mreg1 = -1e30f, lreg0 = 0.f, lreg1 = 0.f;
    #pragma unroll
    for (int m = 0; m < 8; m++) {
        Of[m][0] = Of[m][1] = Of[m][2] = Of[m][3] = 0.f;
    }

    for (int n0 = 0; n0 < Mc; n0 += 128) {
        __syncthreads();   // previous tile (and Q load on iter 0) consumed
        int myv = 0;
        if (t < 128) {
            int mv = mbase[n0 + t];
            mb[t] = mv ? 0.f : -1e30f;
            myv = (mv != 0);
        }
        int any = __syncthreads_or(myv);
        if (!any) continue;

        // load K, V -> fp16 smem
        for (int idx = t; idx < 2048; idx += 256) {
            int r = idx >> 4, sg = idx & 15;
            float4 kv = *(const float4*)(kbase + (size_t)(n0 + r) * QKVN + sg * 4);
            __half* pk = Kh + r * AHS + sg * 4;
            *(uint32_t*)(pk)     = h2u(kv.x, kv.y);
            *(uint32_t*)(pk + 2) = h2u(kv.z, kv.w);
            float4 vv = *(const float4*)(vbase + (size_t)(n0 + r) * QKVN + sg * 4);
            __half* pv = Vh + r * AHS + sg * 4;
            *(uint32_t*)(pv)     = h2u(vv.x, vv.y);
            *(uint32_t*)(pv + 2) = h2u(vv.z, vv.w);
        }
        __syncthreads();

        // Q fragments for this warp (once per tile)
        uint32_t af[4][4];
        {
            uint32_t aq = sQ + (uint32_t)(((w * 16 + (lane & 15)) * AHS) + ((lane >> 4) & 1) * 8) * 2;
            #pragma unroll
            for (int c = 0; c < 4; c++)
                LDSM_X4(af[c][0], af[c][1], af[c][2], af[c][3], aq + c * 32);
        }

        // S = Q . K^T  (16 n-tiles of 8 keys)
        #pragma unroll
        for (int j = 0; j < 16; j++) {
            float* S = Sf[j];
            S[0] = S[1] = S[2] = S[3] = 0.f;
            uint32_t kb = sK + (uint32_t)(((8 * j + (lane & 7)) * AHS) + ((lane >> 3) & 1) * 8) * 2;
            #pragma unroll
            for (int c = 0; c < 4; c++) {
                uint32_t bb[2];
                LDSM_X2(bb[0], bb[1], kb + c * 32);
                mma_f16(S, af[c], bb);
            }
            // mask bias (cols 8j+2tig, 8j+2tig+1)
            float2 mm = *(float2*)&mb[8 * j + 2 * tig];
            S[0] += mm.x; S[1] += mm.y; S[2] += mm.x; S[3] += mm.y;
        }

        // online softmax: rows gid (c0,c1), gid+8 (c2,c3)
        float tm0 = -1e30f, tm1 = -1e30f;
        #pragma unroll
        for (int j = 0; j < 16; j++) {
            tm0 = fmaxf(tm0, fmaxf(Sf[j][0], Sf[j][1]));
            tm1 = fmaxf(tm1, fmaxf(Sf[j][2], Sf[j][3]));
        }
        tm0 = fmaxf(tm0, __shfl_xor_sync(0xffffffffu, tm0, 1));
        tm0 = fmaxf(tm0, __shfl_xor_sync(0xffffffffu, tm0, 2));
        tm1 = fmaxf(tm1, __shfl_xor_sync(0xffffffffu, tm1, 1));
        tm1 = fmaxf(tm1, __shfl_xor_sync(0xffffffffu, tm1, 2));

        float mn0 = fmaxf(mreg0, tm0);
        float mn1 = fmaxf(mreg1, tm1);
        float sc0 = __expf(mreg0 - mn0);
        float sc1 = __expf(mreg1 - mn1);
        float rs0 = 0.f, rs1 = 0.f;
        #pragma unroll
        for (int j = 0; j < 16; j++) {
            Sf[j][0] = __expf(Sf[j][0] - mn0);
            Sf[j][1] = __expf(Sf[j][1] - mn0);
            Sf[j][2] = __expf(Sf[j][2] - mn1);
            Sf[j][3] = __expf(Sf[j][3] - mn1);
            rs0 += Sf[j][0] + Sf[j][1];
            rs1 += Sf[j][2] + Sf[j][3];
        }
        rs0 += __shfl_xor_sync(0xffffffffu, rs0, 1);
        rs0 += __shfl_xor_sync(0xffffffffu, rs0, 2);
        rs1 += __shfl_xor_sync(0xffffffffu, rs1, 1);
        rs1 += __shfl_xor_sync(0xffffffffu, rs1, 2);
        lreg0 = lreg0 * sc0 + rs0;
        lreg1 = lreg1 * sc1 + rs1;
        mreg0 = mn0; mreg1 = mn1;

        #pragma unroll
        for (int m = 0; m < 8; m++) {
            Of[m][0] *= sc0; Of[m][1] *= sc0;
            Of[m][2] *= sc1; Of[m][3] *= sc1;
        }

        // O += P . V  (P from S fragments, V via ldmatrix.trans)
        #pragma unroll
        for (int c = 0; c < 8; c++) {
            uint32_t pa[4];
            pa[0] = h2u(Sf[2 * c][0],     Sf[2 * c][1]);
            pa[1] = h2u(Sf[2 * c][2],     Sf[2 * c][3]);
            pa[2] = h2u(Sf[2 * c + 1][0], Sf[2 * c + 1][1]);
            pa[3] = h2u(Sf[2 * c + 1][2], Sf[2 * c + 1][3]);
            uint32_t vb = sV + (uint32_t)(((16 * c + (lane & 15)) * AHS)) * 2;
            #pragma unroll
            for (int m = 0; m < 8; m++) {
                uint32_t bb[2];
                LDSM_X2T(bb[0], bb[1], vb + m * 16);
                mma_f16(Of[m], pa, bb);
            }
        }
    }

    // normalize + store fp16
    float inv0 = 1.0f / lreg0;
    float inv1 = 1.0f / lreg1;
    const int r0 = m0 + w * 16 + gid;
    #pragma unroll
    for (int m = 0; m < 8; m++) {
        int cc = 8 * m + 2 * tig;
        __half* op0 = out + (size_t)(b * Mc + r0) * Dc + h * DHc + cc;
        __half* op1 = op0 + (size_t)8 * Dc;
        uint32_t u0 = h2u(Of[m][0] * inv0, Of[m][1] * inv0);
        uint32_t u1 = h2u(Of[m][2] * inv1, Of[m][3] * inv1);
        *(uint32_t*)op0 = u0;
        *(uint32_t*)op1 = u1;
    }
}

// ---------------- GeGLU (exact gelu * gate, fp16 out) ----------------
__global__ void geglu_kernel(const float* __restrict__ g, __half* __restrict__ act) {
    int idx = blockIdx.x * blockDim.x + threadIdx.x;
    if (idx >= ROWS * FFc) return;
    int r = idx / FFc;
    int j = idx - r * FFc;
    float x    = g[(size_t)r * WIN + j];
    float gate = g[(size_t)r * WIN + FFc + j];
    float ge = 0.5f * x * (1.0f + erff(x * 0.7071067811865476f));
    act[idx] = __float2half_rn(ge * gate);
}

// ---------------- launch ----------------
extern "C" void kernel_launch(void* const* d_in, const int* in_sizes, int n_in,
                              void* d_out, int out_size) {
    const float* x     = (const float*)d_in[0];
    const int*   mask  = (const int*)  d_in[1];
    const float* ln1w  = (const float*)d_in[2];
    const float* ln1b  = (const float*)d_in[3];
    const float* wqkv  = (const float*)d_in[4];
    const float* bqkv  = (const float*)d_in[5];
    const float* wo    = (const float*)d_in[6];
    const float* ln2w  = (const float*)d_in[7];
    const float* ln2b  = (const float*)d_in[8];
    const float* wi    = (const float*)d_in[9];
    const float* womlp = (const float*)d_in[10];
    float* out = (float*)d_out;

    float *qkvb, *x1, *gb;
    __half *xn, *attn, *hb, *actb, *wq, *wO, *wI, *wOM;
    cudaGetSymbolAddress((void**)&qkvb, g_qkv);
    cudaGetSymbolAddress((void**)&x1,   g_x1);
    cudaGetSymbolAddress((void**)&gb,   g_g);
    cudaGetSymbolAddress((void**)&xn,   h_xn);
    cudaGetSymbolAddress((void**)&attn, h_attn);
    cudaGetSymbolAddress((void**)&hb,   h_h);
    cudaGetSymbolAddress((void**)&actb, h_act);
    cudaGetSymbolAddress((void**)&wq,   hw_qkv);
    cudaGetSymbolAddress((void**)&wO,   hw_o);
    cudaGetSymbolAddress((void**)&wI,   hw_i);
    cudaGetSymbolAddress((void**)&wOM,  hw_om);

    cudaFuncSetAttribute(attn2_kernel, cudaFuncAttributeMaxDynamicSharedMemorySize,
                         ATTN2_SMEM);

    // 0. weight conversions
    wcvt<<<(QKVN * Dc / 4 + 255) / 256, 256>>>(wqkv, wq, QKVN * Dc / 4);
    wcvt<<<(Dc * Dc / 4 + 255) / 256, 256>>>(wo, wO, Dc * Dc / 4);
    wcvt<<<((int)((size_t)WIN * Dc / 4) + 255) / 256, 256>>>(wi, wI, (int)((size_t)WIN * Dc / 4));
    wcvt<<<(Dc * FFc / 4 + 255) / 256, 256>>>(womlp, wOM, Dc * FFc / 4);

    // 1. LN1 -> fp16
    ln_kernel<<<ROWS, 256>>>(x, ln1w, ln1b, xn);
    // 2. QKV projection (+bias), fp32 out
    gemm_h2<<<dim3(QKVN / 128, ROWS / 128), 256>>>(xn, wq, bqkv, nullptr, qkvb, QKVN, Dc);
    // 3. RoPE
    rope_kernel<<<(ROWS * Hc * (DHc / 2) + 255) / 256, 256>>>(qkvb);
    // 4. Attention (HMMA flash) -> fp16
    attn2_kernel<<<dim3(Mc / 128, Hc, Bc), 256, ATTN2_SMEM>>>(qkvb, mask, attn);
    // 5. WO projection + residual(x) -> fp32 x1
    gemm_h2<<<dim3(Dc / 128, ROWS / 128), 256>>>(attn, wO, nullptr, x, x1, Dc, Dc);
    // 6. LN2 -> fp16
    ln_kernel<<<ROWS, 256>>>(x1, ln2w, ln2b, hb);
    // 7. WI projection -> fp32 g
    gemm_h2<<<dim3(WIN / 128, ROWS / 128), 256>>>(hb, wI, nullptr, nullptr, gb, WIN, Dc);
    // 8. GeGLU -> fp16
    geglu_kernel<<<(ROWS * FFc + 255) / 256, 256>>>(gb, actb);
    // 9. WO_MLP projection + residual(x1) -> out
    gemm_h2<<<dim3(Dc / 128, ROWS / 128), 256>>>(actb, wOM, nullptr, x1, out, Dc, FFc);
}